// round 4
// baseline (speedup 1.0000x reference)
#include <cuda_runtime.h>
#include <math.h>

// ---------------------------------------------------------------------------
// Scratch (static __device__ arrays; no dynamic allocation allowed)
// ---------------------------------------------------------------------------
#define MAX_E 800000
#define MAX_N 50048

__device__ __align__(16) float    g_logits[MAX_E];
__device__ __align__(16) unsigned g_segmax[MAX_N];
__device__ __align__(16) float    g_segsum[MAX_N];
__device__ __align__(16) float    g_cnt[MAX_N];
__device__ __align__(16) float    g_agg[50000 * 64];

// orderable-key mapping for float atomicMax
__device__ __forceinline__ unsigned f2key(float f) {
    unsigned b = __float_as_uint(f);
    return b ^ (unsigned)(((int)b >> 31) | 0x80000000);
}
__device__ __forceinline__ float key2f(unsigned k) {
    unsigned b = k ^ ((k & 0x80000000u) ? 0x80000000u : 0xFFFFFFFFu);
    return __uint_as_float(b);
}

__device__ __forceinline__ void red_add_v4(float* p, float4 v) {
    asm volatile("red.global.add.v4.f32 [%0], {%1,%2,%3,%4};"
                 :: "l"(__cvta_generic_to_global(p)),
                    "f"(v.x), "f"(v.y), "f"(v.z), "f"(v.w)
                 : "memory");
}

// ---------------------------------------------------------------------------
// K0: zero-init scratch
// ---------------------------------------------------------------------------
__global__ void k0_init(int N) {
    int i = blockIdx.x * blockDim.x + threadIdx.x;
    if (i < N) {
        g_segmax[i] = 0u;     // key-space -inf
        g_segsum[i] = 0.0f;
        g_cnt[i]    = 0.0f;
    }
    if (i < N * 64) g_agg[i] = 0.0f;
}

// ---------------------------------------------------------------------------
// K1: fused edge kernel.
//   tile: 128 edges. GEMM1: X[128x192] @ W1cat[192x256] (in 4 N-chunks of 64)
//   chunks 0,1 -> ReLU -> GEMM2 into uef accumulators (We2)
//   chunks 2,3 -> ReLU -> dot with Wa2 -> logits
//   epilogue: write uef (+be2), write logits, atomicMax segmax, atomicAdd cnt
// Shared memory layout (floats):
//   sX  [192][128]   24576
//   sW  [32][64]      2048
//   sH  [64][132]     8448
//   sWe2[128][64]     8192
//   sLog[128]          128
// ---------------------------------------------------------------------------
#define EDGE_SMEM_FLOATS (24576 + 2048 + 8448 + 8192 + 128)
#define EDGE_SMEM_BYTES  (EDGE_SMEM_FLOATS * 4)

__global__ __launch_bounds__(256, 1)
void k1_edge(const float* __restrict__ nf,  const float* __restrict__ ef,
             const float* __restrict__ We1, const float* __restrict__ be1,
             const float* __restrict__ We2, const float* __restrict__ be2,
             const float* __restrict__ Wa1, const float* __restrict__ ba1,
             const float* __restrict__ Wa2, const float* __restrict__ ba2,
             const int* __restrict__ src,   const int* __restrict__ dst,
             float* __restrict__ uef_out, int E)
{
    extern __shared__ float sm[];
    float* sX   = sm;                 // [192][128]
    float* sW   = sX + 24576;         // [32][64]
    float* sH   = sW + 2048;          // [64][132]
    float* sWe2 = sH + 8448;          // [128][64]
    float* sLog = sWe2 + 8192;        // [128]

    const int tid = threadIdx.x;
    const int tx  = tid & 15;
    const int ty  = tid >> 4;
    const int e0  = blockIdx.x * 128;

    // stage We2 (32 KB)
    #pragma unroll
    for (int i = tid; i < 2048; i += 256)
        ((float4*)sWe2)[i] = ((const float4*)We2)[i];
    if (tid < 128) sLog[tid] = 0.0f;

    // gather X tile, transposed into sX[k][m]
    #pragma unroll 4
    for (int it = 0; it < 24; ++it) {
        int task = it * 256 + tid;
        int m = task & 127;
        int s = task >> 7;            // 0..47 (float4 segment)
        int e = e0 + m;
        float4 v = make_float4(0.f, 0.f, 0.f, 0.f);
        if (e < E) {
            if (s < 16)      v = *(const float4*)&ef[(size_t)e * 64 + s * 4];
            else if (s < 32) { int r = src[e]; v = *(const float4*)&nf[(size_t)r * 64 + (s - 16) * 4]; }
            else             { int r = dst[e]; v = *(const float4*)&nf[(size_t)r * 64 + (s - 32) * 4]; }
        }
        int k0 = s * 4;
        sX[(k0 + 0) * 128 + m] = v.x;
        sX[(k0 + 1) * 128 + m] = v.y;
        sX[(k0 + 2) * 128 + m] = v.z;
        sX[(k0 + 3) * 128 + m] = v.w;
    }
    __syncthreads();

    float uacc[8][4];
    #pragma unroll
    for (int i = 0; i < 8; ++i)
        #pragma unroll
        for (int j = 0; j < 4; ++j) uacc[i][j] = 0.0f;

    #pragma unroll 1
    for (int chunk = 0; chunk < 4; ++chunk) {
        const float* W1 = (chunk < 2) ? We1 : Wa1;
        const float* b1 = (chunk < 2) ? be1 : ba1;
        const int c0 = (chunk & 1) * 64;

        float acc[8][4];
        #pragma unroll
        for (int i = 0; i < 8; ++i)
            #pragma unroll
            for (int j = 0; j < 4; ++j) acc[i][j] = 0.0f;

        #pragma unroll 1
        for (int kc = 0; kc < 6; ++kc) {
            __syncthreads();
            #pragma unroll
            for (int i = tid; i < 512; i += 256) {
                int row = i >> 4;
                int cq  = i & 15;
                *(float4*)&sW[row * 64 + cq * 4] =
                    *(const float4*)&W1[(size_t)(kc * 32 + row) * 128 + c0 + cq * 4];
            }
            __syncthreads();
            #pragma unroll
            for (int kk = 0; kk < 32; ++kk) {
                const float* xr = &sX[(kc * 32 + kk) * 128 + ty * 8];
                float4 a0 = *(const float4*)xr;
                float4 a1 = *(const float4*)(xr + 4);
                float4 b  = *(const float4*)&sW[kk * 64 + tx * 4];
                float a[8] = {a0.x, a0.y, a0.z, a0.w, a1.x, a1.y, a1.z, a1.w};
                #pragma unroll
                for (int i = 0; i < 8; ++i) {
                    acc[i][0] += a[i] * b.x;
                    acc[i][1] += a[i] * b.y;
                    acc[i][2] += a[i] * b.z;
                    acc[i][3] += a[i] * b.w;
                }
            }
        }

        // bias + ReLU
        float bj0 = b1[c0 + tx * 4 + 0], bj1 = b1[c0 + tx * 4 + 1];
        float bj2 = b1[c0 + tx * 4 + 2], bj3 = b1[c0 + tx * 4 + 3];
        #pragma unroll
        for (int i = 0; i < 8; ++i) {
            acc[i][0] = fmaxf(acc[i][0] + bj0, 0.0f);
            acc[i][1] = fmaxf(acc[i][1] + bj1, 0.0f);
            acc[i][2] = fmaxf(acc[i][2] + bj2, 0.0f);
            acc[i][3] = fmaxf(acc[i][3] + bj3, 0.0f);
        }

        if (chunk < 2) {
            // store H chunk transposed to sH[c][m], then GEMM2 partial
            #pragma unroll
            for (int i = 0; i < 8; ++i) {
                sH[(tx * 4 + 0) * 132 + ty * 8 + i] = acc[i][0];
                sH[(tx * 4 + 1) * 132 + ty * 8 + i] = acc[i][1];
                sH[(tx * 4 + 2) * 132 + ty * 8 + i] = acc[i][2];
                sH[(tx * 4 + 3) * 132 + ty * 8 + i] = acc[i][3];
            }
            __syncthreads();
            #pragma unroll
            for (int hh = 0; hh < 64; ++hh) {
                const float* hr = &sH[hh * 132 + ty * 8];
                float4 a0 = *(const float4*)hr;
                float4 a1 = *(const float4*)(hr + 4);
                float4 b  = *(const float4*)&sWe2[(chunk * 64 + hh) * 64 + tx * 4];
                float a[8] = {a0.x, a0.y, a0.z, a0.w, a1.x, a1.y, a1.z, a1.w};
                #pragma unroll
                for (int i = 0; i < 8; ++i) {
                    uacc[i][0] += a[i] * b.x;
                    uacc[i][1] += a[i] * b.y;
                    uacc[i][2] += a[i] * b.z;
                    uacc[i][3] += a[i] * b.w;
                }
            }
        } else {
            float w0 = Wa2[(chunk - 2) * 64 + tx * 4 + 0];
            float w1 = Wa2[(chunk - 2) * 64 + tx * 4 + 1];
            float w2 = Wa2[(chunk - 2) * 64 + tx * 4 + 2];
            float w3 = Wa2[(chunk - 2) * 64 + tx * 4 + 3];
            #pragma unroll
            for (int i = 0; i < 8; ++i) {
                float p = acc[i][0] * w0 + acc[i][1] * w1 + acc[i][2] * w2 + acc[i][3] * w3;
                p += __shfl_xor_sync(0xFFFFFFFFu, p, 1);
                p += __shfl_xor_sync(0xFFFFFFFFu, p, 2);
                p += __shfl_xor_sync(0xFFFFFFFFu, p, 4);
                p += __shfl_xor_sync(0xFFFFFFFFu, p, 8);
                if (tx == 0) sLog[ty * 8 + i] += p;
            }
        }
    }
    __syncthreads();

    // uef epilogue (+ be2)
    float o0 = be2[tx * 4 + 0], o1 = be2[tx * 4 + 1];
    float o2 = be2[tx * 4 + 2], o3 = be2[tx * 4 + 3];
    #pragma unroll
    for (int i = 0; i < 8; ++i) {
        int e = e0 + ty * 8 + i;
        if (e < E) {
            float4 o = make_float4(uacc[i][0] + o0, uacc[i][1] + o1,
                                   uacc[i][2] + o2, uacc[i][3] + o3);
            *(float4*)&uef_out[(size_t)e * 64 + tx * 4] = o;
        }
    }

    // logits + segment max + count
    if (tid < 128) {
        int e = e0 + tid;
        if (e < E) {
            float lg = sLog[tid] + ba2[0];
            g_logits[e] = lg;
            int d = dst[e];
            atomicMax(&g_segmax[d], f2key(lg));
            atomicAdd(&g_cnt[d], 1.0f);
        }
    }
}

// ---------------------------------------------------------------------------
// K2: per-edge exp + unnormalized attention-weighted accumulate
//     agg[dst] += exp(logit - segmax[dst]) * uef[e]  (normalize in K3)
//     16 lanes per edge (float4 each)
// ---------------------------------------------------------------------------
__global__ void k2_agg(const float* __restrict__ uef, const int* __restrict__ dst, int E)
{
    int gid = blockIdx.x * blockDim.x + threadIdx.x;
    int e = gid >> 4;
    if (e >= E) return;
    int l = gid & 15;
    int d = dst[e];
    float mx = key2f(g_segmax[d]);
    float ex = __expf(g_logits[e] - mx);
    if (l == 0) atomicAdd(&g_segsum[d], ex);
    float4 u = *(const float4*)&uef[(size_t)e * 64 + l * 4];
    float4 v = make_float4(u.x * ex, u.y * ex, u.z * ex, u.w * ex);
    red_add_v4(&g_agg[(size_t)d * 64 + l * 4], v);
}

// ---------------------------------------------------------------------------
// K3: node MLP.  X2 = [agg/(segsum*cnt) | nf]  [128-wide K], hidden 128, out 64
// Shared: sX[128][128] 16384, sW[32][64] 2048, sH[64][132] 8448,
//         sWn2[128][64] 8192, sRs[128] 128
// ---------------------------------------------------------------------------
#define NODE_SMEM_FLOATS (16384 + 2048 + 8448 + 8192 + 128)
#define NODE_SMEM_BYTES  (NODE_SMEM_FLOATS * 4)

__global__ __launch_bounds__(256, 1)
void k3_node(const float* __restrict__ nf,
             const float* __restrict__ Wn1, const float* __restrict__ bn1,
             const float* __restrict__ Wn2, const float* __restrict__ bn2,
             float* __restrict__ unf_out, int N)
{
    extern __shared__ float sm[];
    float* sX   = sm;            // [128][128]
    float* sW   = sX + 16384;    // [32][64]
    float* sH   = sW + 2048;     // [64][132]
    float* sWn2 = sH + 8448;     // [128][64]
    float* sRs  = sWn2 + 8192;   // [128]

    const int tid = threadIdx.x;
    const int tx  = tid & 15;
    const int ty  = tid >> 4;
    const int n0  = blockIdx.x * 128;

    #pragma unroll
    for (int i = tid; i < 2048; i += 256)
        ((float4*)sWn2)[i] = ((const float4*)Wn2)[i];
    if (tid < 128) {
        int n = n0 + tid;
        float rs = 0.0f;
        if (n < N) {
            float c = g_cnt[n];
            if (c > 0.5f) rs = 1.0f / (g_segsum[n] * c);
        }
        sRs[tid] = rs;
    }
    __syncthreads();

    // gather X2 transposed
    #pragma unroll 4
    for (int it = 0; it < 16; ++it) {
        int task = it * 256 + tid;
        int m = task & 127;
        int s = task >> 7;    // 0..31
        int n = n0 + m;
        float4 v = make_float4(0.f, 0.f, 0.f, 0.f);
        if (n < N) {
            if (s < 16) {
                v = *(const float4*)&g_agg[(size_t)n * 64 + s * 4];
                float rs = sRs[m];
                v.x *= rs; v.y *= rs; v.z *= rs; v.w *= rs;
            } else {
                v = *(const float4*)&nf[(size_t)n * 64 + (s - 16) * 4];
            }
        }
        int k0 = s * 4;
        sX[(k0 + 0) * 128 + m] = v.x;
        sX[(k0 + 1) * 128 + m] = v.y;
        sX[(k0 + 2) * 128 + m] = v.z;
        sX[(k0 + 3) * 128 + m] = v.w;
    }
    __syncthreads();

    float uacc[8][4];
    #pragma unroll
    for (int i = 0; i < 8; ++i)
        #pragma unroll
        for (int j = 0; j < 4; ++j) uacc[i][j] = 0.0f;

    #pragma unroll 1
    for (int chunk = 0; chunk < 2; ++chunk) {
        const int c0 = chunk * 64;
        float acc[8][4];
        #pragma unroll
        for (int i = 0; i < 8; ++i)
            #pragma unroll
            for (int j = 0; j < 4; ++j) acc[i][j] = 0.0f;

        #pragma unroll 1
        for (int kc = 0; kc < 4; ++kc) {
            __syncthreads();
            #pragma unroll
            for (int i = tid; i < 512; i += 256) {
                int row = i >> 4;
                int cq  = i & 15;
                *(float4*)&sW[row * 64 + cq * 4] =
                    *(const float4*)&Wn1[(size_t)(kc * 32 + row) * 128 + c0 + cq * 4];
            }
            __syncthreads();
            #pragma unroll
            for (int kk = 0; kk < 32; ++kk) {
                const float* xr = &sX[(kc * 32 + kk) * 128 + ty * 8];
                float4 a0 = *(const float4*)xr;
                float4 a1 = *(const float4*)(xr + 4);
                float4 b  = *(const float4*)&sW[kk * 64 + tx * 4];
                float a[8] = {a0.x, a0.y, a0.z, a0.w, a1.x, a1.y, a1.z, a1.w};
                #pragma unroll
                for (int i = 0; i < 8; ++i) {
                    acc[i][0] += a[i] * b.x;
                    acc[i][1] += a[i] * b.y;
                    acc[i][2] += a[i] * b.z;
                    acc[i][3] += a[i] * b.w;
                }
            }
        }

        float bj0 = bn1[c0 + tx * 4 + 0], bj1 = bn1[c0 + tx * 4 + 1];
        float bj2 = bn1[c0 + tx * 4 + 2], bj3 = bn1[c0 + tx * 4 + 3];
        #pragma unroll
        for (int i = 0; i < 8; ++i) {
            acc[i][0] = fmaxf(acc[i][0] + bj0, 0.0f);
            acc[i][1] = fmaxf(acc[i][1] + bj1, 0.0f);
            acc[i][2] = fmaxf(acc[i][2] + bj2, 0.0f);
            acc[i][3] = fmaxf(acc[i][3] + bj3, 0.0f);
        }

        #pragma unroll
        for (int i = 0; i < 8; ++i) {
            sH[(tx * 4 + 0) * 132 + ty * 8 + i] = acc[i][0];
            sH[(tx * 4 + 1) * 132 + ty * 8 + i] = acc[i][1];
            sH[(tx * 4 + 2) * 132 + ty * 8 + i] = acc[i][2];
            sH[(tx * 4 + 3) * 132 + ty * 8 + i] = acc[i][3];
        }
        __syncthreads();
        #pragma unroll
        for (int hh = 0; hh < 64; ++hh) {
            const float* hr = &sH[hh * 132 + ty * 8];
            float4 a0 = *(const float4*)hr;
            float4 a1 = *(const float4*)(hr + 4);
            float4 b  = *(const float4*)&sWn2[(c0 + hh) * 64 + tx * 4];
            float a[8] = {a0.x, a0.y, a0.z, a0.w, a1.x, a1.y, a1.z, a1.w};
            #pragma unroll
            for (int i = 0; i < 8; ++i) {
                uacc[i][0] += a[i] * b.x;
                uacc[i][1] += a[i] * b.y;
                uacc[i][2] += a[i] * b.z;
                uacc[i][3] += a[i] * b.w;
            }
        }
    }

    float o0 = bn2[tx * 4 + 0], o1 = bn2[tx * 4 + 1];
    float o2 = bn2[tx * 4 + 2], o3 = bn2[tx * 4 + 3];
    #pragma unroll
    for (int i = 0; i < 8; ++i) {
        int n = n0 + ty * 8 + i;
        if (n < N) {
            float4 o = make_float4(uacc[i][0] + o0, uacc[i][1] + o1,
                                   uacc[i][2] + o2, uacc[i][3] + o3);
            *(float4*)&unf_out[(size_t)n * 64 + tx * 4] = o;
        }
    }
}

// ---------------------------------------------------------------------------
// launch
// ---------------------------------------------------------------------------
extern "C" void kernel_launch(void* const* d_in, const int* in_sizes, int n_in,
                              void* d_out, int out_size)
{
    const float* nf  = (const float*)d_in[0];
    const float* ef  = (const float*)d_in[1];
    const float* We1 = (const float*)d_in[2];
    const float* be1 = (const float*)d_in[3];
    const float* We2 = (const float*)d_in[4];
    const float* be2 = (const float*)d_in[5];
    const float* Wa1 = (const float*)d_in[6];
    const float* ba1 = (const float*)d_in[7];
    const float* Wa2 = (const float*)d_in[8];
    const float* ba2 = (const float*)d_in[9];
    const float* Wn1 = (const float*)d_in[10];
    const float* bn1 = (const float*)d_in[11];
    const float* Wn2 = (const float*)d_in[12];
    const float* bn2 = (const float*)d_in[13];
    const int*   src = (const int*)d_in[14];
    const int*   dst = (const int*)d_in[15];

    const int N = in_sizes[0] / 64;
    const int E = in_sizes[14];

    float* unf_out = (float*)d_out;                       // [N,64] first (ref return order)
    float* uef_out = (float*)d_out + (size_t)N * 64;      // [E,64] second

    cudaFuncSetAttribute(k1_edge, cudaFuncAttributeMaxDynamicSharedMemorySize, EDGE_SMEM_BYTES);
    cudaFuncSetAttribute(k3_node, cudaFuncAttributeMaxDynamicSharedMemorySize, NODE_SMEM_BYTES);

    k0_init<<<(N * 64 + 255) / 256, 256>>>(N);
    k1_edge<<<(E + 127) / 128, 256, EDGE_SMEM_BYTES>>>(
        nf, ef, We1, be1, We2, be2, Wa1, ba1, Wa2, ba2, src, dst, uef_out, E);
    k2_agg<<<((long long)E * 16 + 255) / 256, 256>>>(uef_out, dst, E);
    k3_node<<<(N + 127) / 128, 256, NODE_SMEM_BYTES>>>(
        nf, Wn1, bn1, Wn2, bn2, unf_out, N);
}

// round 6
// speedup vs baseline: 1.0935x; 1.0935x over previous
#include <cuda_runtime.h>
#include <math.h>

// ---------------------------------------------------------------------------
// Scratch (static __device__ arrays; no dynamic allocation allowed)
// ---------------------------------------------------------------------------
#define MAX_N 50048

__device__ __align__(16) float g_segsum[MAX_N];
__device__ __align__(16) float g_cnt[MAX_N];
__device__ __align__(16) float g_agg[50000 * 64];

typedef unsigned long long u64;

// packed fp32x2 FMA (FFMA2) — ptxas never emits this from C++; PTX-only.
#define FMA2(d, a, b) asm("fma.rn.f32x2 %0, %1, %2, %0;" : "+l"(d) : "l"(a), "l"(b))
// duplicate one f32 into both lanes of a packed f32x2
#define DUP2(d, s)    asm("mov.b64 %0, {%1, %1};" : "=l"(d) : "f"(s))

union F4U2 { float4 f; u64 u[2]; };
union U2F  { u64 u; float2 f; };

__device__ __forceinline__ void red_add_v4(float* p, float4 v) {
    asm volatile("red.global.add.v4.f32 [%0], {%1,%2,%3,%4};"
                 :: "l"(__cvta_generic_to_global(p)),
                    "f"(v.x), "f"(v.y), "f"(v.z), "f"(v.w)
                 : "memory");
}

// ---------------------------------------------------------------------------
// K0: zero-init scratch
// ---------------------------------------------------------------------------
__global__ void k0_init(int N) {
    int i = blockIdx.x * blockDim.x + threadIdx.x;
    if (i < N) {
        g_segsum[i] = 0.0f;
        g_cnt[i]    = 0.0f;
    }
    if (i < N * 64) g_agg[i] = 0.0f;
}

// ---------------------------------------------------------------------------
// K1: fused edge kernel (GEMM1 -> ReLU -> GEMM2/attn-dot), FFMA2 inner loops.
//   epilogue: ex = exp(logit) (no max-subtraction; logits are O(1)),
//   write uef, atomicAdd segsum/cnt, red.add ex*uef into g_agg.
// Shared (floats): sX[192][128] 24576, sW[32][64] 2048, sH[64][132] 8448,
//                  sWe2[128][64] 8192, sLog[128] 128
// ---------------------------------------------------------------------------
#define EDGE_SMEM_FLOATS (24576 + 2048 + 8448 + 8192 + 128)
#define EDGE_SMEM_BYTES  (EDGE_SMEM_FLOATS * 4)

__global__ __launch_bounds__(256, 1)
void k1_edge(const float* __restrict__ nf,  const float* __restrict__ ef,
             const float* __restrict__ We1, const float* __restrict__ be1,
             const float* __restrict__ We2, const float* __restrict__ be2,
             const float* __restrict__ Wa1, const float* __restrict__ ba1,
             const float* __restrict__ Wa2, const float* __restrict__ ba2,
             const int* __restrict__ src,   const int* __restrict__ dst,
             float* __restrict__ uef_out, int E)
{
    extern __shared__ float sm[];
    float* sX   = sm;                 // [192][128]
    float* sW   = sX + 24576;         // [32][64]
    float* sH   = sW + 2048;          // [64][132]
    float* sWe2 = sH + 8448;          // [128][64]
    float* sLog = sWe2 + 8192;        // [128]

    const int tid = threadIdx.x;
    const int tx  = tid & 15;
    const int ty  = tid >> 4;
    const int e0  = blockIdx.x * 128;

    // stage We2 (32 KB)
    #pragma unroll
    for (int i = tid; i < 2048; i += 256)
        ((float4*)sWe2)[i] = ((const float4*)We2)[i];
    if (tid < 128) sLog[tid] = 0.0f;

    // gather X tile, transposed into sX[k][m]
    #pragma unroll 4
    for (int it = 0; it < 24; ++it) {
        int task = it * 256 + tid;
        int m = task & 127;
        int s = task >> 7;            // 0..47 (float4 segment)
        int e = e0 + m;
        float4 v = make_float4(0.f, 0.f, 0.f, 0.f);
        if (e < E) {
            if (s < 16)      v = *(const float4*)&ef[(size_t)e * 64 + s * 4];
            else if (s < 32) { int r = src[e]; v = *(const float4*)&nf[(size_t)r * 64 + (s - 16) * 4]; }
            else             { int r = dst[e]; v = *(const float4*)&nf[(size_t)r * 64 + (s - 32) * 4]; }
        }
        int k0 = s * 4;
        sX[(k0 + 0) * 128 + m] = v.x;
        sX[(k0 + 1) * 128 + m] = v.y;
        sX[(k0 + 2) * 128 + m] = v.z;
        sX[(k0 + 3) * 128 + m] = v.w;
    }
    __syncthreads();

    // uef accumulators: 8 rows x 2 packed col-pairs
    u64 uacc2[8][2];
    #pragma unroll
    for (int i = 0; i < 8; ++i) { uacc2[i][0] = 0ull; uacc2[i][1] = 0ull; }

    #pragma unroll 1
    for (int chunk = 0; chunk < 4; ++chunk) {
        const float* W1 = (chunk < 2) ? We1 : Wa1;
        const float* b1 = (chunk < 2) ? be1 : ba1;
        const int c0 = (chunk & 1) * 64;

        u64 acc2[8][2];
        #pragma unroll
        for (int i = 0; i < 8; ++i) { acc2[i][0] = 0ull; acc2[i][1] = 0ull; }

        #pragma unroll 1
        for (int kc = 0; kc < 6; ++kc) {
            __syncthreads();
            #pragma unroll
            for (int i = tid; i < 512; i += 256) {
                int row = i >> 4;
                int cq  = i & 15;
                *(float4*)&sW[row * 64 + cq * 4] =
                    *(const float4*)&W1[(size_t)(kc * 32 + row) * 128 + c0 + cq * 4];
            }
            __syncthreads();
            #pragma unroll
            for (int kk = 0; kk < 32; ++kk) {
                const float* xr = &sX[(kc * 32 + kk) * 128 + ty * 8];
                float4 a0 = *(const float4*)xr;
                float4 a1 = *(const float4*)(xr + 4);
                F4U2 B; B.f = *(const float4*)&sW[kk * 64 + tx * 4];
                u64 ad[8];
                DUP2(ad[0], a0.x); DUP2(ad[1], a0.y); DUP2(ad[2], a0.z); DUP2(ad[3], a0.w);
                DUP2(ad[4], a1.x); DUP2(ad[5], a1.y); DUP2(ad[6], a1.z); DUP2(ad[7], a1.w);
                #pragma unroll
                for (int i = 0; i < 8; ++i) {
                    FMA2(acc2[i][0], ad[i], B.u[0]);
                    FMA2(acc2[i][1], ad[i], B.u[1]);
                }
            }
        }

        // unpack + bias + ReLU
        float acc[8][4];
        #pragma unroll
        for (int i = 0; i < 8; ++i) {
            U2F p0, p1; p0.u = acc2[i][0]; p1.u = acc2[i][1];
            acc[i][0] = p0.f.x; acc[i][1] = p0.f.y;
            acc[i][2] = p1.f.x; acc[i][3] = p1.f.y;
        }
        float bj0 = b1[c0 + tx * 4 + 0], bj1 = b1[c0 + tx * 4 + 1];
        float bj2 = b1[c0 + tx * 4 + 2], bj3 = b1[c0 + tx * 4 + 3];
        #pragma unroll
        for (int i = 0; i < 8; ++i) {
            acc[i][0] = fmaxf(acc[i][0] + bj0, 0.0f);
            acc[i][1] = fmaxf(acc[i][1] + bj1, 0.0f);
            acc[i][2] = fmaxf(acc[i][2] + bj2, 0.0f);
            acc[i][3] = fmaxf(acc[i][3] + bj3, 0.0f);
        }

        if (chunk < 2) {
            // store H chunk transposed to sH[c][m], then GEMM2 partial (FFMA2)
            #pragma unroll
            for (int i = 0; i < 8; ++i) {
                sH[(tx * 4 + 0) * 132 + ty * 8 + i] = acc[i][0];
                sH[(tx * 4 + 1) * 132 + ty * 8 + i] = acc[i][1];
                sH[(tx * 4 + 2) * 132 + ty * 8 + i] = acc[i][2];
                sH[(tx * 4 + 3) * 132 + ty * 8 + i] = acc[i][3];
            }
            __syncthreads();
            #pragma unroll
            for (int hh = 0; hh < 64; ++hh) {
                const float* hr = &sH[hh * 132 + ty * 8];
                float4 a0 = *(const float4*)hr;
                float4 a1 = *(const float4*)(hr + 4);
                F4U2 B; B.f = *(const float4*)&sWe2[(chunk * 64 + hh) * 64 + tx * 4];
                u64 ad[8];
                DUP2(ad[0], a0.x); DUP2(ad[1], a0.y); DUP2(ad[2], a0.z); DUP2(ad[3], a0.w);
                DUP2(ad[4], a1.x); DUP2(ad[5], a1.y); DUP2(ad[6], a1.z); DUP2(ad[7], a1.w);
                #pragma unroll
                for (int i = 0; i < 8; ++i) {
                    FMA2(uacc2[i][0], ad[i], B.u[0]);
                    FMA2(uacc2[i][1], ad[i], B.u[1]);
                }
            }
        } else {
            float w0 = Wa2[(chunk - 2) * 64 + tx * 4 + 0];
            float w1 = Wa2[(chunk - 2) * 64 + tx * 4 + 1];
            float w2 = Wa2[(chunk - 2) * 64 + tx * 4 + 2];
            float w3 = Wa2[(chunk - 2) * 64 + tx * 4 + 3];
            #pragma unroll
            for (int i = 0; i < 8; ++i) {
                float p = acc[i][0] * w0 + acc[i][1] * w1 + acc[i][2] * w2 + acc[i][3] * w3;
                p += __shfl_xor_sync(0xFFFFFFFFu, p, 1);
                p += __shfl_xor_sync(0xFFFFFFFFu, p, 2);
                p += __shfl_xor_sync(0xFFFFFFFFu, p, 4);
                p += __shfl_xor_sync(0xFFFFFFFFu, p, 8);
                if (tx == 0) sLog[ty * 8 + i] += p;
            }
        }
    }
    __syncthreads();

    // ---- epilogue: exp(logit), segsum/cnt atomics (reuse sW as sExp/sDst) ----
    float* sExpF = sW;               // [128]
    int*   sDstI = (int*)(sW + 128); // [128]
    if (tid < 128) {
        int e = e0 + tid;
        if (e < E) {
            float lg = sLog[tid] + ba2[0];
            float ex = __expf(lg);          // no max-subtraction: logits are O(1)
            sExpF[tid] = ex;
            int d = dst[e];
            sDstI[tid] = d;
            atomicAdd(&g_segsum[d], ex);
            atomicAdd(&g_cnt[d], 1.0f);
        }
    }
    __syncthreads();

    // uef write (+be2) and unnormalized attention-weighted aggregate
    float o0 = be2[tx * 4 + 0], o1 = be2[tx * 4 + 1];
    float o2 = be2[tx * 4 + 2], o3 = be2[tx * 4 + 3];
    #pragma unroll
    for (int i = 0; i < 8; ++i) {
        int m = ty * 8 + i;
        int e = e0 + m;
        if (e < E) {
            U2F p0, p1; p0.u = uacc2[i][0]; p1.u = uacc2[i][1];
            float4 o = make_float4(p0.f.x + o0, p0.f.y + o1, p1.f.x + o2, p1.f.y + o3);
            *(float4*)&uef_out[(size_t)e * 64 + tx * 4] = o;
            float ex = sExpF[m];
            int   d  = sDstI[m];
            float4 v = make_float4(o.x * ex, o.y * ex, o.z * ex, o.w * ex);
            red_add_v4(&g_agg[(size_t)d * 64 + tx * 4], v);
        }
    }
}

// ---------------------------------------------------------------------------
// K3: node MLP.  X2 = [agg/(segsum*cnt) | nf], hidden 128, out 64 (FFMA2)
// Shared: sX[128][128] 16384, sW[32][64] 2048, sH[64][132] 8448,
//         sWn2[128][64] 8192, sRs[128] 128
// ---------------------------------------------------------------------------
#define NODE_SMEM_FLOATS (16384 + 2048 + 8448 + 8192 + 128)
#define NODE_SMEM_BYTES  (NODE_SMEM_FLOATS * 4)

__global__ __launch_bounds__(256, 1)
void k3_node(const float* __restrict__ nf,
             const float* __restrict__ Wn1, const float* __restrict__ bn1,
             const float* __restrict__ Wn2, const float* __restrict__ bn2,
             float* __restrict__ unf_out, int N)
{
    extern __shared__ float sm[];
    float* sX   = sm;            // [128][128]
    float* sW   = sX + 16384;    // [32][64]
    float* sH   = sW + 2048;     // [64][132]
    float* sWn2 = sH + 8448;     // [128][64]
    float* sRs  = sWn2 + 8192;   // [128]

    const int tid = threadIdx.x;
    const int tx  = tid & 15;
    const int ty  = tid >> 4;
    const int n0  = blockIdx.x * 128;

    #pragma unroll
    for (int i = tid; i < 2048; i += 256)
        ((float4*)sWn2)[i] = ((const float4*)Wn2)[i];
    if (tid < 128) {
        int n = n0 + tid;
        float rs = 0.0f;
        if (n < N) {
            float c = g_cnt[n];
            if (c > 0.5f) rs = 1.0f / (g_segsum[n] * c);
        }
        sRs[tid] = rs;
    }
    __syncthreads();

    // gather X2 transposed
    #pragma unroll 4
    for (int it = 0; it < 16; ++it) {
        int task = it * 256 + tid;
        int m = task & 127;
        int s = task >> 7;    // 0..31
        int n = n0 + m;
        float4 v = make_float4(0.f, 0.f, 0.f, 0.f);
        if (n < N) {
            if (s < 16) {
                v = *(const float4*)&g_agg[(size_t)n * 64 + s * 4];
                float rs = sRs[m];
                v.x *= rs; v.y *= rs; v.z *= rs; v.w *= rs;
            } else {
                v = *(const float4*)&nf[(size_t)n * 64 + (s - 16) * 4];
            }
        }
        int k0 = s * 4;
        sX[(k0 + 0) * 128 + m] = v.x;
        sX[(k0 + 1) * 128 + m] = v.y;
        sX[(k0 + 2) * 128 + m] = v.z;
        sX[(k0 + 3) * 128 + m] = v.w;
    }
    __syncthreads();

    u64 uacc2[8][2];
    #pragma unroll
    for (int i = 0; i < 8; ++i) { uacc2[i][0] = 0ull; uacc2[i][1] = 0ull; }

    #pragma unroll 1
    for (int chunk = 0; chunk < 2; ++chunk) {
        const int c0 = chunk * 64;
        u64 acc2[8][2];
        #pragma unroll
        for (int i = 0; i < 8; ++i) { acc2[i][0] = 0ull; acc2[i][1] = 0ull; }

        #pragma unroll 1
        for (int kc = 0; kc < 4; ++kc) {
            __syncthreads();
            #pragma unroll
            for (int i = tid; i < 512; i += 256) {
                int row = i >> 4;
                int cq  = i & 15;
                *(float4*)&sW[row * 64 + cq * 4] =
                    *(const float4*)&Wn1[(size_t)(kc * 32 + row) * 128 + c0 + cq * 4];
            }
            __syncthreads();
            #pragma unroll
            for (int kk = 0; kk < 32; ++kk) {
                const float* xr = &sX[(kc * 32 + kk) * 128 + ty * 8];
                float4 a0 = *(const float4*)xr;
                float4 a1 = *(const float4*)(xr + 4);
                F4U2 B; B.f = *(const float4*)&sW[kk * 64 + tx * 4];
                u64 ad[8];
                DUP2(ad[0], a0.x); DUP2(ad[1], a0.y); DUP2(ad[2], a0.z); DUP2(ad[3], a0.w);
                DUP2(ad[4], a1.x); DUP2(ad[5], a1.y); DUP2(ad[6], a1.z); DUP2(ad[7], a1.w);
                #pragma unroll
                for (int i = 0; i < 8; ++i) {
                    FMA2(acc2[i][0], ad[i], B.u[0]);
                    FMA2(acc2[i][1], ad[i], B.u[1]);
                }
            }
        }

        float acc[8][4];
        #pragma unroll
        for (int i = 0; i < 8; ++i) {
            U2F p0, p1; p0.u = acc2[i][0]; p1.u = acc2[i][1];
            acc[i][0] = p0.f.x; acc[i][1] = p0.f.y;
            acc[i][2] = p1.f.x; acc[i][3] = p1.f.y;
        }
        float bj0 = bn1[c0 + tx * 4 + 0], bj1 = bn1[c0 + tx * 4 + 1];
        float bj2 = bn1[c0 + tx * 4 + 2], bj3 = bn1[c0 + tx * 4 + 3];
        #pragma unroll
        for (int i = 0; i < 8; ++i) {
            acc[i][0] = fmaxf(acc[i][0] + bj0, 0.0f);
            acc[i][1] = fmaxf(acc[i][1] + bj1, 0.0f);
            acc[i][2] = fmaxf(acc[i][2] + bj2, 0.0f);
            acc[i][3] = fmaxf(acc[i][3] + bj3, 0.0f);
        }

        #pragma unroll
        for (int i = 0; i < 8; ++i) {
            sH[(tx * 4 + 0) * 132 + ty * 8 + i] = acc[i][0];
            sH[(tx * 4 + 1) * 132 + ty * 8 + i] = acc[i][1];
            sH[(tx * 4 + 2) * 132 + ty * 8 + i] = acc[i][2];
            sH[(tx * 4 + 3) * 132 + ty * 8 + i] = acc[i][3];
        }
        __syncthreads();
        #pragma unroll
        for (int hh = 0; hh < 64; ++hh) {
            const float* hr = &sH[hh * 132 + ty * 8];
            float4 a0 = *(const float4*)hr;
            float4 a1 = *(const float4*)(hr + 4);
            F4U2 B; B.f = *(const float4*)&sWn2[(c0 + hh) * 64 + tx * 4];
            u64 ad[8];
            DUP2(ad[0], a0.x); DUP2(ad[1], a0.y); DUP2(ad[2], a0.z); DUP2(ad[3], a0.w);
            DUP2(ad[4], a1.x); DUP2(ad[5], a1.y); DUP2(ad[6], a1.z); DUP2(ad[7], a1.w);
            #pragma unroll
            for (int i = 0; i < 8; ++i) {
                FMA2(uacc2[i][0], ad[i], B.u[0]);
                FMA2(uacc2[i][1], ad[i], B.u[1]);
            }
        }
    }

    float o0 = bn2[tx * 4 + 0], o1 = bn2[tx * 4 + 1];
    float o2 = bn2[tx * 4 + 2], o3 = bn2[tx * 4 + 3];
    #pragma unroll
    for (int i = 0; i < 8; ++i) {
        int n = n0 + ty * 8 + i;
        if (n < N) {
            U2F p0, p1; p0.u = uacc2[i][0]; p1.u = uacc2[i][1];
            float4 o = make_float4(p0.f.x + o0, p0.f.y + o1, p1.f.x + o2, p1.f.y + o3);
            *(float4*)&unf_out[(size_t)n * 64 + tx * 4] = o;
        }
    }
}

// ---------------------------------------------------------------------------
// launch
// ---------------------------------------------------------------------------
extern "C" void kernel_launch(void* const* d_in, const int* in_sizes, int n_in,
                              void* d_out, int out_size)
{
    const float* nf  = (const float*)d_in[0];
    const float* ef  = (const float*)d_in[1];
    const float* We1 = (const float*)d_in[2];
    const float* be1 = (const float*)d_in[3];
    const float* We2 = (const float*)d_in[4];
    const float* be2 = (const float*)d_in[5];
    const float* Wa1 = (const float*)d_in[6];
    const float* ba1 = (const float*)d_in[7];
    const float* Wa2 = (const float*)d_in[8];
    const float* ba2 = (const float*)d_in[9];
    const float* Wn1 = (const float*)d_in[10];
    const float* bn1 = (const float*)d_in[11];
    const float* Wn2 = (const float*)d_in[12];
    const float* bn2 = (const float*)d_in[13];
    const int*   src = (const int*)d_in[14];
    const int*   dst = (const int*)d_in[15];

    const int N = in_sizes[0] / 64;
    const int E = in_sizes[14];

    float* unf_out = (float*)d_out;                       // [N,64] first (ref return order)
    float* uef_out = (float*)d_out + (size_t)N * 64;      // [E,64] second

    cudaFuncSetAttribute(k1_edge, cudaFuncAttributeMaxDynamicSharedMemorySize, EDGE_SMEM_BYTES);
    cudaFuncSetAttribute(k3_node, cudaFuncAttributeMaxDynamicSharedMemorySize, NODE_SMEM_BYTES);

    k0_init<<<(N * 64 + 255) / 256, 256>>>(N);
    k1_edge<<<(E + 127) / 128, 256, EDGE_SMEM_BYTES>>>(
        nf, ef, We1, be1, We2, be2, Wa1, ba1, Wa2, ba2, src, dst, uef_out, E);
    k3_node<<<(N + 127) / 128, 256, NODE_SMEM_BYTES>>>(
        nf, Wn1, bn1, Wn2, bn2, unf_out, N);
}